// round 1
// baseline (speedup 1.0000x reference)
#include <cuda_runtime.h>

// Problem constants (match reference: K=161 freq bins, T=2000 frames)
#define KBINS 161
#define TFRAMES 2000

// out[j,t] = sum_i w(i,j,t) * x[i,t]
// wide (|m|>1):  w = max(am - |j-i|, 0) / S(i,t),  S analytic
// narrow:        w = delta(i==j)
__global__ void __launch_bounds__(192, 8) smooth_kernel(
    const float* __restrict__ m,
    const float* __restrict__ x,
    float* __restrict__ out)
{
    const int t = blockIdx.x;
    const int j = threadIdx.x;

    __shared__ float s_am[KBINS];   // |m| for wide bins, else 0-contribution path
    __shared__ float s_xs[KBINS];   // x/S for wide bins, 0 for narrow
    __shared__ float s_xn[KBINS];   // x for narrow bins (delta term), 0 for wide
    __shared__ int   s_R;

    if (j == 0) s_R = 0;
    __syncthreads();

    int myD = 0;
    if (j < KBINS) {
        const float a  = fabsf(m[j * TFRAMES + t]);
        const float xv = x[j * TFRAMES + t];
        const bool wide = a > 1.0f;
        if (wide) {
            int D = (int)ceilf(a) - 1;           // # positive integer offsets per side
            if (D < 0) D = 0;
            if (D > KBINS - 1) D = KBINS - 1;
            myD = D;
            const int   dl = min(D, j);
            const int   dr = min(D, KBINS - 1 - j);
            const float fl = (float)dl, fr = (float)dr;
            // S = a + sum_{d=1..dl}(a-d) + sum_{d=1..dr}(a-d)
            const float S = a + (fl * a - 0.5f * fl * (fl + 1.0f))
                              + (fr * a - 0.5f * fr * (fr + 1.0f));
            s_am[j] = a;
            s_xs[j] = xv / S;
            s_xn[j] = 0.0f;
        } else {
            s_am[j] = 0.0f;   // value irrelevant: s_xs==0 kills the product
            s_xs[j] = 0.0f;
            s_xn[j] = xv;     // delta contribution (normalized delta == delta)
        }
    }

    // block max of D -> gather radius
    // warp reduce then one atomic per warp
    unsigned mask = 0xFFFFFFFFu;
    #pragma unroll
    for (int off = 16; off > 0; off >>= 1)
        myD = max(myD, __shfl_xor_sync(mask, myD, off));
    if ((threadIdx.x & 31) == 0) atomicMax(&s_R, myD);
    __syncthreads();

    if (j < KBINS) {
        const int R  = s_R;
        const int lo = max(0, j - R);
        const int hi = min(KBINS - 1, j + R);
        float acc = s_xn[j];                 // delta term if this bin is narrow
        for (int i = lo; i <= hi; ++i) {
            const float w = s_am[i] - fabsf((float)(i - j));
            acc = fmaf(fmaxf(w, 0.0f), s_xs[i], acc);
        }
        out[j * TFRAMES + t] = acc;
    }
}

extern "C" void kernel_launch(void* const* d_in, const int* in_sizes, int n_in,
                              void* d_out, int out_size)
{
    const float* m = (const float*)d_in[0];   // (K, T, 1) fp32
    const float* x = (const float*)d_in[1];   // (1, 1, K, T) fp32
    // d_in[2] = input_length (int32), unused: T is fixed by tensor shapes
    float* out = (float*)d_out;               // (1, 1, K, T) fp32

    smooth_kernel<<<TFRAMES, 192>>>(m, x, out);
}

// round 2
// speedup vs baseline: 1.2694x; 1.2694x over previous
#include <cuda_runtime.h>

#define KBINS   161
#define TFRAMES 2000
#define TT      16          // time frames per block tile
#define TQ      (TT / 4)    // float4 chunks per row
#define NV      (KBINS * TQ)
#define NBLK    (TFRAMES / TT)   // 125
#define NTHR    512

__device__ __forceinline__ void prep_elem(float mv, float xv, int k,
                                          float& am, float& xs, float& xn,
                                          int& myD)
{
    const float a = fabsf(mv);
    if (a > 1.0f) {
        int D = (int)ceilf(a) - 1;
        D = max(0, min(D, KBINS - 1));
        myD = max(myD, D);
        const float fl = (float)min(D, k);
        const float fr = (float)min(D, KBINS - 1 - k);
        // S = a + sum_{d=1..fl}(a-d) + sum_{d=1..fr}(a-d)
        const float S = a + (fl * a - 0.5f * fl * (fl + 1.0f))
                          + (fr * a - 0.5f * fr * (fr + 1.0f));
        am = a;
        xs = __fdividef(xv, S);
        xn = 0.0f;
    } else {
        am = 0.0f;   // contributes nothing: xs == 0
        xs = 0.0f;
        xn = xv;     // delta passthrough
    }
}

__global__ void __launch_bounds__(NTHR, 2) smooth_kernel(
    const float* __restrict__ m,
    const float* __restrict__ x,
    float* __restrict__ out)
{
    const int t0  = blockIdx.x * TT;
    const int tid = threadIdx.x;

    __shared__ float4 s_am[KBINS][TQ];
    __shared__ float4 s_xs[KBINS][TQ];
    __shared__ float4 s_xn[KBINS][TQ];
    __shared__ int    s_R;

    if (tid == 0) s_R = 0;
    __syncthreads();

    // ---- load + preprocess (coalesced float4 along t) ----
    int myD = 0;
    for (int v = tid; v < NV; v += NTHR) {
        const int k = v >> 2;
        const int q = v & 3;
        const int g = k * TFRAMES + t0 + 4 * q;
        const float4 m4 = *(const float4*)(m + g);
        const float4 x4 = *(const float4*)(x + g);
        float4 am, xs, xn;
        prep_elem(m4.x, x4.x, k, am.x, xs.x, xn.x, myD);
        prep_elem(m4.y, x4.y, k, am.y, xs.y, xn.y, myD);
        prep_elem(m4.z, x4.z, k, am.z, xs.z, xn.z, myD);
        prep_elem(m4.w, x4.w, k, am.w, xs.w, xn.w, myD);
        s_am[k][q] = am;
        s_xs[k][q] = xs;
        s_xn[k][q] = xn;
    }

    // block max of window radius
    #pragma unroll
    for (int off = 16; off > 0; off >>= 1)
        myD = max(myD, __shfl_xor_sync(0xFFFFFFFFu, myD, off));
    if ((tid & 31) == 0) atomicMax(&s_R, myD);
    __syncthreads();

    const int R = s_R;

    // ---- gather + store (coalesced float4 along t) ----
    for (int v = tid; v < NV; v += NTHR) {
        const int j = v >> 2;
        const int q = v & 3;
        float4 acc = s_xn[j][q];
        for (int d = -R; d <= R; ++d) {
            const int  i  = j + d;
            const bool ok = (unsigned)i < (unsigned)KBINS;
            const int  ic = ok ? i : 0;
            const float wd = ok ? fabsf((float)d) : 3.0e38f;
            const float4 am4 = s_am[ic][q];
            const float4 xs4 = s_xs[ic][q];
            acc.x = fmaf(fmaxf(am4.x - wd, 0.0f), xs4.x, acc.x);
            acc.y = fmaf(fmaxf(am4.y - wd, 0.0f), xs4.y, acc.y);
            acc.z = fmaf(fmaxf(am4.z - wd, 0.0f), xs4.z, acc.z);
            acc.w = fmaf(fmaxf(am4.w - wd, 0.0f), xs4.w, acc.w);
        }
        *(float4*)(out + j * TFRAMES + t0 + 4 * q) = acc;
    }
}

extern "C" void kernel_launch(void* const* d_in, const int* in_sizes, int n_in,
                              void* d_out, int out_size)
{
    const float* m = (const float*)d_in[0];   // (K, T, 1) fp32
    const float* x = (const float*)d_in[1];   // (1, 1, K, T) fp32
    float* out = (float*)d_out;               // (1, 1, K, T) fp32

    smooth_kernel<<<NBLK, NTHR>>>(m, x, out);
}